// round 13
// baseline (speedup 1.0000x reference)
#include <cuda_runtime.h>

// Problem constants
#define BB      8
#define II      32
#define CC      8
#define OO      16
#define HHD     16          // pose dim h
#define MM      256         // OO*HHD
#define HW      256         // H*W
#define NROUTE  3

#define PPB     4           // pixels per block
#define THREADS 1024
#define VROW    33          // votes row pad (i stride): conflict-free scalar LDS/STS
#define VP      (MM*VROW)   // per-pixel votes region = 8448
#define LROW    17          // logits i-stride
#define LP      (II*LROW)   // per-pixel logits = 544
#define RROW    36          // route row stride (float4-aligned, bank-clean)
#define RP      (OO*RROW)   // per-pixel route = 576

// Shared memory layout (float offsets)
static constexpr int SM_VOT   = 0;                        // [4][8448] = 33792
static constexpr int SM_SX    = SM_VOT  + PPB * VP;       // [4][256]  = 1024 (aliased as s_act at the end)
static constexpr int SM_LOG   = SM_SX   + PPB * MM;       // [4][544]  = 2176
static constexpr int SM_ROUTE = SM_LOG  + PPB * LP;       // [4][576]  = 2304
static constexpr int SM_BIAS  = SM_ROUTE+ PPB * RP;       // [256]
static constexpr int SM_TOTAL = SM_BIAS + MM;             // 39552 floats = 158208 B

__global__ __launch_bounds__(THREADS, 1)
void caps_routing_kernel(const float* __restrict__ x,
                         const float* __restrict__ w,
                         const float* __restrict__ bias,
                         float* __restrict__ out)
{
    extern __shared__ float sm[];
    float* s_votes = sm + SM_VOT;     // [p][m*33 + i]
    float* s_sx    = sm + SM_SX;      // [p][i*8+c]  (phase 1 only; reused as s_act)
    float* s_log   = sm + SM_LOG;     // [p][i*17 + o]
    float* s_route = sm + SM_ROUTE;   // [p][o*36 + i]
    float* s_bias  = sm + SM_BIAS;

    const int t        = threadIdx.x;
    const int pixblock = blockIdx.x * PPB;
    const int b        = pixblock >> 8;        // PPB divides 256 -> same b for whole block
    const int pix0     = pixblock & 255;       // multiple of 4 -> float4-aligned

    const int m  = t & 255;        // o*16 + hh
    const int g  = t >> 8;         // phase 1: i-group (8 i's). phase 2: pixel p.
    const int o  = m >> 4;
    const int hh = m & 15;
    // bit-reversed hh: which value index this lane ends up owning after the butterfly
    const int irev = ((hh & 1) << 3) | (((hh >> 1) & 1) << 2)
                   | (((hh >> 2) & 1) << 1) | ((hh >> 3) & 1);

    // ---- init: bias + vectorized x-slice (float4 over 4 pixels) ----
    if (t < MM) {
        s_bias[t] = bias[t];
        const int i = t >> 3;
        const int c = t & 7;
        const float4 xv = *(const float4*)(x + (((b * II + i) * CC + c) << 8) + pix0);
        s_sx[0 * 256 + t] = xv.x;
        s_sx[1 * 256 + t] = xv.y;
        s_sx[2 * 256 + t] = xv.z;
        s_sx[3 * 256 + t] = xv.w;
    }
    __syncthreads();

    // ---- phase 1: votes -> smem. Thread (m, g) computes i in [g*8, g*8+8). ----
    {
        const int i0 = g * 8;
        #pragma unroll
        for (int il = 0; il < 8; ++il) {
            const int i = i0 + il;
            const float* wp = w + (i * CC) * MM + m;
            float wreg[CC];
            #pragma unroll
            for (int c = 0; c < CC; ++c) wreg[c] = wp[c * MM];   // coalesced across m
            #pragma unroll
            for (int p = 0; p < PPB; ++p) {
                const float4* sx4 = (const float4*)(s_sx + p * 256 + i * 8);
                float4 s0 = sx4[0], s1 = sx4[1];                 // broadcast
                float vv = s0.x * wreg[0] + s0.y * wreg[1] + s0.z * wreg[2] + s0.w * wreg[3]
                         + s1.x * wreg[4] + s1.y * wreg[5] + s1.z * wreg[6] + s1.w * wreg[7];
                s_votes[p * VP + m * VROW + i] = vv;             // stride-33 lanes: bank-clean
            }
        }
    }
    __syncthreads();

    // ---- phase 2: thread (p = g, m) owns all 32 i for its (pixel, m) ----
    const int p = g;
    float v[II];
    #pragma unroll
    for (int i = 0; i < II; ++i) v[i] = s_votes[p * VP + m * VROW + i];  // bank-clean

    float act;

    // ======== iteration 0: route is uniformly 1/16 (softmax of zeros) ========
    {
        float acc = 0.f;
        #pragma unroll
        for (int i = 0; i < II; ++i) acc += v[i];
        acc = s_bias[m] + acc * 0.0625f;

        float ns = acc * acc;
        ns += __shfl_xor_sync(0xffffffffu, ns, 1);
        ns += __shfl_xor_sync(0xffffffffu, ns, 2);
        ns += __shfl_xor_sync(0xffffffffu, ns, 4);
        ns += __shfl_xor_sync(0xffffffffu, ns, 8);
        float scale = sqrtf(ns) / (1.0f + ns);
        act = acc * scale;

        // distance -> WRITE logits (they start at zero; this covers every entry)
        #pragma unroll
        for (int half = 0; half < 2; ++half) {
            float dv[16];
            #pragma unroll
            for (int j = 0; j < 16; ++j) dv[j] = v[half * 16 + j] * act;
            {   int hb = hh & 1;
                #pragma unroll
                for (int j = 0; j < 8; ++j) {
                    float send = hb ? dv[j] : dv[j + 8];
                    float recv = __shfl_xor_sync(0xffffffffu, send, 1);
                    dv[j] = (hb ? dv[j + 8] : dv[j]) + recv;
                } }
            {   int hb = (hh >> 1) & 1;
                #pragma unroll
                for (int j = 0; j < 4; ++j) {
                    float send = hb ? dv[j] : dv[j + 4];
                    float recv = __shfl_xor_sync(0xffffffffu, send, 2);
                    dv[j] = (hb ? dv[j + 4] : dv[j]) + recv;
                } }
            {   int hb = (hh >> 2) & 1;
                #pragma unroll
                for (int j = 0; j < 2; ++j) {
                    float send = hb ? dv[j] : dv[j + 2];
                    float recv = __shfl_xor_sync(0xffffffffu, send, 4);
                    dv[j] = (hb ? dv[j + 2] : dv[j]) + recv;
                } }
            {   int hb = (hh >> 3) & 1;
                float send = hb ? dv[0] : dv[1];
                float recv = __shfl_xor_sync(0xffffffffu, send, 8);
                dv[0] = (hb ? dv[1] : dv[0]) + recv;
            }
            s_log[p * LP + (half * 16 + irev) * LROW + o] = dv[0];
        }
    }
    __syncthreads();

    // ======== iterations 1..NROUTE-1 ========
    #pragma unroll
    for (int r = 1; r < NROUTE; ++r) {
        // softmax over O per (p, i): 128 rows x 8 threads (ALL 1024 threads)
        {
            const int row = t >> 3;           // 0..127
            const int j   = t & 7;
            const int sp  = row >> 5;
            const int si  = row & 31;
            const float* lg = s_log + sp * LP + si * LROW;
            float l0 = lg[j];
            float l1 = lg[j + 8];
            float mx = fmaxf(l0, l1);
            mx = fmaxf(mx, __shfl_xor_sync(0xffffffffu, mx, 1));
            mx = fmaxf(mx, __shfl_xor_sync(0xffffffffu, mx, 2));
            mx = fmaxf(mx, __shfl_xor_sync(0xffffffffu, mx, 4));
            float e0 = __expf(l0 - mx);
            float e1 = __expf(l1 - mx);
            float s = e0 + e1;
            s += __shfl_xor_sync(0xffffffffu, s, 1);
            s += __shfl_xor_sync(0xffffffffu, s, 2);
            s += __shfl_xor_sync(0xffffffffu, s, 4);
            float inv = 1.0f / s;
            float* rt = s_route + sp * RP;
            rt[j * RROW + si]       = e0 * inv;   // bank-clean (verified)
            rt[(j + 8) * RROW + si] = e1 * inv;
        }
        __syncthreads();

        // preact: in-register reduce over all 32 i
        {
            const float4* rp = (const float4*)(s_route + p * RP + o * RROW);
            float acc = s_bias[m];
            #pragma unroll
            for (int q = 0; q < 8; ++q) {
                float4 r4 = rp[q];                // broadcast (2 addrs per warp)
                acc += r4.x * v[4 * q + 0];
                acc += r4.y * v[4 * q + 1];
                acc += r4.z * v[4 * q + 2];
                acc += r4.w * v[4 * q + 3];
            }
            float ns = acc * acc;
            ns += __shfl_xor_sync(0xffffffffu, ns, 1);
            ns += __shfl_xor_sync(0xffffffffu, ns, 2);
            ns += __shfl_xor_sync(0xffffffffu, ns, 4);
            ns += __shfl_xor_sync(0xffffffffu, ns, 8);
            float scale = sqrtf(ns) / (1.0f + ns);
            act = acc * scale;
        }

        if (r < NROUTE - 1) {
            // distance -> ACCUMULATE logits
            #pragma unroll
            for (int half = 0; half < 2; ++half) {
                float dv[16];
                #pragma unroll
                for (int j = 0; j < 16; ++j) dv[j] = v[half * 16 + j] * act;
                {   int hb = hh & 1;
                    #pragma unroll
                    for (int j = 0; j < 8; ++j) {
                        float send = hb ? dv[j] : dv[j + 8];
                        float recv = __shfl_xor_sync(0xffffffffu, send, 1);
                        dv[j] = (hb ? dv[j + 8] : dv[j]) + recv;
                    } }
                {   int hb = (hh >> 1) & 1;
                    #pragma unroll
                    for (int j = 0; j < 4; ++j) {
                        float send = hb ? dv[j] : dv[j + 4];
                        float recv = __shfl_xor_sync(0xffffffffu, send, 2);
                        dv[j] = (hb ? dv[j + 4] : dv[j]) + recv;
                    } }
                {   int hb = (hh >> 2) & 1;
                    #pragma unroll
                    for (int j = 0; j < 2; ++j) {
                        float send = hb ? dv[j] : dv[j + 2];
                        float recv = __shfl_xor_sync(0xffffffffu, send, 4);
                        dv[j] = (hb ? dv[j + 2] : dv[j]) + recv;
                    } }
                {   int hb = (hh >> 3) & 1;
                    float send = hb ? dv[0] : dv[1];
                    float recv = __shfl_xor_sync(0xffffffffu, send, 8);
                    dv[0] = (hb ? dv[1] : dv[0]) + recv;
                }
                s_log[p * LP + (half * 16 + irev) * LROW + o] += dv[0];
            }
            __syncthreads();
        }
    }

    // ---- stage act through smem (alias over dead s_sx) and store coalesced ----
    float* s_act = s_sx;               // s_sx is dead after phase 1
    s_act[p * 256 + m] = act;          // each address written by exactly one thread
    __syncthreads();
    if (t < MM) {
        float4 o4 = make_float4(s_act[0 * 256 + t], s_act[1 * 256 + t],
                                s_act[2 * 256 + t], s_act[3 * 256 + t]);
        *(float4*)(out + ((b * MM + t) << 8) + pix0) = o4;
    }
}

extern "C" void kernel_launch(void* const* d_in, const int* in_sizes, int n_in,
                              void* d_out, int out_size)
{
    const float* x    = (const float*)d_in[0];   // (8,32,8,16,16)
    const float* w    = (const float*)d_in[1];   // (32,8,256)
    const float* bias = (const float*)d_in[2];   // (16,16,1,1)
    float* out = (float*)d_out;                  // (8,16,16,16,16)

    static bool attr_set = false;
    if (!attr_set) {
        cudaFuncSetAttribute(caps_routing_kernel,
                             cudaFuncAttributeMaxDynamicSharedMemorySize,
                             SM_TOTAL * (int)sizeof(float));
        attr_set = true;
    }

    const int n_pixels = BB * HW;                 // 2048
    dim3 grid(n_pixels / PPB);                    // 512 blocks, 1 per SM wave-slot
    dim3 block(THREADS);
    caps_routing_kernel<<<grid, block, SM_TOTAL * (int)sizeof(float)>>>(x, w, bias, out);
}

// round 15
// speedup vs baseline: 1.0742x; 1.0742x over previous
#include <cuda_runtime.h>

// Problem constants
#define BB      8
#define II      32
#define CC      8
#define OO      16
#define HHD     16          // pose dim h
#define MM      256         // OO*HHD
#define HW      256         // H*W
#define NROUTE  3

#define PPB     4           // pixels per block
#define THREADS 1024
#define VROW    33          // votes row pad (i stride): conflict-free scalar LDS/STS
#define VP      (MM*VROW)   // per-pixel votes region = 8448
#define LROW    17          // logits i-stride
#define LP      (II*LROW)   // per-pixel logits = 544
#define RROW    36          // route row stride (float4-aligned, bank-clean)
#define RP      (OO*RROW)   // per-pixel route = 576

// Shared memory layout (float offsets)
static constexpr int SM_VOT   = 0;                        // [4][8448] = 33792
static constexpr int SM_SX    = SM_VOT  + PPB * VP;       // [4][256]  = 1024 (reused as s_act)
static constexpr int SM_LOG   = SM_SX   + PPB * MM;       // [4][544]  = 2176
static constexpr int SM_ROUTE = SM_LOG  + PPB * LP;       // [4][576]  = 2304
static constexpr int SM_BIAS  = SM_ROUTE+ PPB * RP;       // [256]
static constexpr int SM_TOTAL = SM_BIAS + MM;             // 39552 floats = 158208 B

// Group barrier: 256-thread scope, one domain per pixel-group. Groups drift
// apart and fill each other's latency holes (4 virtual CTAs, weights loaded once).
#define BARG(gid) asm volatile("bar.sync %0, 256;" :: "r"((gid) + 1) : "memory")

__global__ __launch_bounds__(THREADS, 1)
void caps_routing_kernel(const float* __restrict__ x,
                         const float* __restrict__ w,
                         const float* __restrict__ bias,
                         float* __restrict__ out)
{
    extern __shared__ float sm[];
    float* s_votes = sm + SM_VOT;     // [p][m*33 + i]
    float* s_sx    = sm + SM_SX;      // [p][i*8+c]  (phase 1 only; reused as s_act)
    float* s_log   = sm + SM_LOG;     // [p][i*17 + o]
    float* s_route = sm + SM_ROUTE;   // [p][o*36 + i]
    float* s_bias  = sm + SM_BIAS;

    const int t        = threadIdx.x;
    const int pixblock = blockIdx.x * PPB;
    const int b        = pixblock >> 8;        // PPB divides 256 -> same b for whole block
    const int pix0     = pixblock & 255;       // multiple of 4 -> float4-aligned

    const int m  = t & 255;        // o*16 + hh
    const int g  = t >> 8;         // phase 1: i-group. phase 2: pixel p AND barrier domain.
    const int o  = m >> 4;
    const int hh = m & 15;
    const int irev = ((hh & 1) << 3) | (((hh >> 1) & 1) << 2)
                   | (((hh >> 2) & 1) << 1) | ((hh >> 3) & 1);

    // ---- init: bias + vectorized x-slice (float4 over 4 pixels) ----
    if (t < MM) {
        s_bias[t] = bias[t];
        const int i = t >> 3;
        const int c = t & 7;
        const float4 xv = *(const float4*)(x + (((b * II + i) * CC + c) << 8) + pix0);
        s_sx[0 * 256 + t] = xv.x;
        s_sx[1 * 256 + t] = xv.y;
        s_sx[2 * 256 + t] = xv.z;
        s_sx[3 * 256 + t] = xv.w;
    }
    __syncthreads();

    // ---- phase 1: votes -> smem. Thread (m, g) computes i in [g*8, g*8+8). ----
    {
        const int i0 = g * 8;
        #pragma unroll
        for (int il = 0; il < 8; ++il) {
            const int i = i0 + il;
            const float* wp = w + (i * CC) * MM + m;
            float wreg[CC];
            #pragma unroll
            for (int c = 0; c < CC; ++c) wreg[c] = wp[c * MM];   // coalesced across m
            #pragma unroll
            for (int p = 0; p < PPB; ++p) {
                const float4* sx4 = (const float4*)(s_sx + p * 256 + i * 8);
                float4 s0 = sx4[0], s1 = sx4[1];                 // broadcast
                float e0 = s0.x * wreg[0] + s0.y * wreg[1];
                float e1 = s0.z * wreg[2] + s0.w * wreg[3];
                float e2 = s1.x * wreg[4] + s1.y * wreg[5];
                float e3 = s1.z * wreg[6] + s1.w * wreg[7];
                s_votes[p * VP + m * VROW + i] = (e0 + e1) + (e2 + e3);
            }
        }
    }
    __syncthreads();

    // ---- phase 2: group g owns pixel p = g entirely (its own barrier domain) ----
    const int p  = g;
    const int tg = t & 255;                    // thread index within group
    float v[II];
    #pragma unroll
    for (int i = 0; i < II; ++i) v[i] = s_votes[p * VP + m * VROW + i];  // bank-clean

    float act;

    // ======== iteration 0: route is uniformly 1/16 (softmax of zeros) ========
    {
        float a0 = 0.f, a1 = 0.f, a2 = 0.f, a3 = 0.f;
        #pragma unroll
        for (int q = 0; q < 8; ++q) {
            a0 += v[4 * q + 0];
            a1 += v[4 * q + 1];
            a2 += v[4 * q + 2];
            a3 += v[4 * q + 3];
        }
        float acc = s_bias[m] + ((a0 + a1) + (a2 + a3)) * 0.0625f;

        float ns = acc * acc;
        ns += __shfl_xor_sync(0xffffffffu, ns, 1);
        ns += __shfl_xor_sync(0xffffffffu, ns, 2);
        ns += __shfl_xor_sync(0xffffffffu, ns, 4);
        ns += __shfl_xor_sync(0xffffffffu, ns, 8);
        float scale = sqrtf(ns) / (1.0f + ns);
        act = acc * scale;

        // distance -> WRITE logits
        #pragma unroll
        for (int half = 0; half < 2; ++half) {
            float dv[16];
            #pragma unroll
            for (int j = 0; j < 16; ++j) dv[j] = v[half * 16 + j] * act;
            {   int hb = hh & 1;
                #pragma unroll
                for (int j = 0; j < 8; ++j) {
                    float send = hb ? dv[j] : dv[j + 8];
                    float recv = __shfl_xor_sync(0xffffffffu, send, 1);
                    dv[j] = (hb ? dv[j + 8] : dv[j]) + recv;
                } }
            {   int hb = (hh >> 1) & 1;
                #pragma unroll
                for (int j = 0; j < 4; ++j) {
                    float send = hb ? dv[j] : dv[j + 4];
                    float recv = __shfl_xor_sync(0xffffffffu, send, 2);
                    dv[j] = (hb ? dv[j + 4] : dv[j]) + recv;
                } }
            {   int hb = (hh >> 2) & 1;
                #pragma unroll
                for (int j = 0; j < 2; ++j) {
                    float send = hb ? dv[j] : dv[j + 2];
                    float recv = __shfl_xor_sync(0xffffffffu, send, 4);
                    dv[j] = (hb ? dv[j + 2] : dv[j]) + recv;
                } }
            {   int hb = (hh >> 3) & 1;
                float send = hb ? dv[0] : dv[1];
                float recv = __shfl_xor_sync(0xffffffffu, send, 8);
                dv[0] = (hb ? dv[1] : dv[0]) + recv;
            }
            s_log[p * LP + (half * 16 + irev) * LROW + o] = dv[0];
        }
    }
    BARG(g);

    // ======== iterations 1..NROUTE-1 (all group-local) ========
    #pragma unroll
    for (int r = 1; r < NROUTE; ++r) {
        // softmax over O, group-local: 32 rows (i) x 8 threads
        {
            const int si = tg >> 3;           // 0..31
            const int j  = tg & 7;
            const float* lg = s_log + p * LP + si * LROW;
            float l0 = lg[j];
            float l1 = lg[j + 8];
            float mx = fmaxf(l0, l1);
            mx = fmaxf(mx, __shfl_xor_sync(0xffffffffu, mx, 1));
            mx = fmaxf(mx, __shfl_xor_sync(0xffffffffu, mx, 2));
            mx = fmaxf(mx, __shfl_xor_sync(0xffffffffu, mx, 4));
            float e0 = __expf(l0 - mx);
            float e1 = __expf(l1 - mx);
            float s = e0 + e1;
            s += __shfl_xor_sync(0xffffffffu, s, 1);
            s += __shfl_xor_sync(0xffffffffu, s, 2);
            s += __shfl_xor_sync(0xffffffffu, s, 4);
            float inv = 1.0f / s;
            float* rt = s_route + p * RP;
            rt[j * RROW + si]       = e0 * inv;
            rt[(j + 8) * RROW + si] = e1 * inv;
        }
        BARG(g);

        // preact: in-register reduce over all 32 i (4 independent FMA chains)
        {
            const float4* rp = (const float4*)(s_route + p * RP + o * RROW);
            float a0 = 0.f, a1 = 0.f, a2 = 0.f, a3 = 0.f;
            #pragma unroll
            for (int q = 0; q < 8; ++q) {
                float4 r4 = rp[q];                // broadcast
                a0 += r4.x * v[4 * q + 0];
                a1 += r4.y * v[4 * q + 1];
                a2 += r4.z * v[4 * q + 2];
                a3 += r4.w * v[4 * q + 3];
            }
            float acc = s_bias[m] + ((a0 + a1) + (a2 + a3));
            float ns = acc * acc;
            ns += __shfl_xor_sync(0xffffffffu, ns, 1);
            ns += __shfl_xor_sync(0xffffffffu, ns, 2);
            ns += __shfl_xor_sync(0xffffffffu, ns, 4);
            ns += __shfl_xor_sync(0xffffffffu, ns, 8);
            float scale = sqrtf(ns) / (1.0f + ns);
            act = acc * scale;
        }

        if (r < NROUTE - 1) {
            // distance -> ACCUMULATE logits
            #pragma unroll
            for (int half = 0; half < 2; ++half) {
                float dv[16];
                #pragma unroll
                for (int j = 0; j < 16; ++j) dv[j] = v[half * 16 + j] * act;
                {   int hb = hh & 1;
                    #pragma unroll
                    for (int j = 0; j < 8; ++j) {
                        float send = hb ? dv[j] : dv[j + 8];
                        float recv = __shfl_xor_sync(0xffffffffu, send, 1);
                        dv[j] = (hb ? dv[j + 8] : dv[j]) + recv;
                    } }
                {   int hb = (hh >> 1) & 1;
                    #pragma unroll
                    for (int j = 0; j < 4; ++j) {
                        float send = hb ? dv[j] : dv[j + 4];
                        float recv = __shfl_xor_sync(0xffffffffu, send, 2);
                        dv[j] = (hb ? dv[j + 4] : dv[j]) + recv;
                    } }
                {   int hb = (hh >> 2) & 1;
                    #pragma unroll
                    for (int j = 0; j < 2; ++j) {
                        float send = hb ? dv[j] : dv[j + 2];
                        float recv = __shfl_xor_sync(0xffffffffu, send, 4);
                        dv[j] = (hb ? dv[j + 2] : dv[j]) + recv;
                    } }
                {   int hb = (hh >> 3) & 1;
                    float send = hb ? dv[0] : dv[1];
                    float recv = __shfl_xor_sync(0xffffffffu, send, 8);
                    dv[0] = (hb ? dv[1] : dv[0]) + recv;
                }
                s_log[p * LP + (half * 16 + irev) * LROW + o] += dv[0];
            }
            BARG(g);
        }
    }

    // ---- stage act through smem (alias over dead s_sx) and store coalesced ----
    float* s_act = s_sx;               // s_sx is dead after phase 1
    s_act[p * 256 + m] = act;
    __syncthreads();                   // cross-group: re-converges all domains
    if (t < MM) {
        float4 o4 = make_float4(s_act[0 * 256 + t], s_act[1 * 256 + t],
                                s_act[2 * 256 + t], s_act[3 * 256 + t]);
        *(float4*)(out + ((b * MM + t) << 8) + pix0) = o4;
    }
}

extern "C" void kernel_launch(void* const* d_in, const int* in_sizes, int n_in,
                              void* d_out, int out_size)
{
    const float* x    = (const float*)d_in[0];   // (8,32,8,16,16)
    const float* w    = (const float*)d_in[1];   // (32,8,256)
    const float* bias = (const float*)d_in[2];   // (16,16,1,1)
    float* out = (float*)d_out;                  // (8,16,16,16,16)

    static bool attr_set = false;
    if (!attr_set) {
        cudaFuncSetAttribute(caps_routing_kernel,
                             cudaFuncAttributeMaxDynamicSharedMemorySize,
                             SM_TOTAL * (int)sizeof(float));
        attr_set = true;
    }

    const int n_pixels = BB * HW;                 // 2048
    dim3 grid(n_pixels / PPB);                    // 512
    dim3 block(THREADS);
    caps_routing_kernel<<<grid, block, SM_TOTAL * (int)sizeof(float)>>>(x, w, bias, out);
}

// round 17
// speedup vs baseline: 1.2601x; 1.1731x over previous
#include <cuda_runtime.h>

// Problem constants
#define BB      8
#define II      32
#define CC      8
#define OO      16
#define HHD     16          // pose dim h
#define MM      256         // OO*HHD
#define HW      256         // H*W
#define NROUTE  3

#define PPB     4           // pixels per block
#define THREADS 1024
#define VP      (II*MM)     // per-pixel votes region = 8192 floats, layout [i*256 + m]
#define LROW    17          // logits i-stride
#define LP      (II*LROW)   // per-pixel logits = 544
#define RROW    36          // route row stride (float4-aligned, bank-clean)
#define RP      (OO*RROW)   // per-pixel route = 576

// Shared memory layout (float offsets)
static constexpr int SM_VOT   = 0;                        // [4][8192] = 32768
static constexpr int SM_SX    = SM_VOT  + PPB * VP;       // [4][256]  = 1024 (reused as s_act)
static constexpr int SM_LOG   = SM_SX   + PPB * MM;       // [4][544]  = 2176
static constexpr int SM_ROUTE = SM_LOG  + PPB * LP;       // [4][576]  = 2304
static constexpr int SM_BIAS  = SM_ROUTE+ PPB * RP;       // [256]
static constexpr int SM_TOTAL = SM_BIAS + MM;             // 38528 floats = 154112 B

// Group barrier: 256-thread scope, one domain per pixel-group.
#define BARG(gid) asm volatile("bar.sync %0, 256;" :: "r"((gid) + 1) : "memory")

__device__ __forceinline__ float frcp_(float x) {
    float r; asm("rcp.approx.f32 %0, %1;" : "=f"(r) : "f"(x)); return r;
}
__device__ __forceinline__ float frsq_(float x) {
    float r; asm("rsqrt.approx.f32 %0, %1;" : "=f"(r) : "f"(x)); return r;
}

__global__ __launch_bounds__(THREADS, 1)
void caps_routing_kernel(const float* __restrict__ x,
                         const float* __restrict__ w,
                         const float* __restrict__ bias,
                         float* __restrict__ out)
{
    extern __shared__ float sm[];
    float* s_votes = sm + SM_VOT;     // [p][i*256 + m]  (unpadded; all accesses lane-consecutive in m)
    float* s_sx    = sm + SM_SX;      // [p][i*8+c]  (phase 1 only; reused as s_act)
    float* s_log   = sm + SM_LOG;     // [p][i*17 + o]
    float* s_route = sm + SM_ROUTE;   // [p][o*36 + i]
    float* s_bias  = sm + SM_BIAS;

    const int t        = threadIdx.x;
    const int pixblock = blockIdx.x * PPB;
    const int b        = pixblock >> 8;        // PPB divides 256 -> same b for whole block
    const int pix0     = pixblock & 255;       // multiple of 4 -> float4-aligned

    const int m  = t & 255;        // phase 2: o*16 + hh
    const int g  = t >> 8;         // phase 2: pixel p AND barrier domain
    const int o  = m >> 4;
    const int hh = m & 15;
    const int irev = ((hh & 1) << 3) | (((hh >> 1) & 1) << 2)
                   | (((hh >> 2) & 1) << 1) | ((hh >> 3) & 1);

    // ---- init: bias + vectorized x-slice (float4 over 4 pixels) ----
    if (t < MM) {
        s_bias[t] = bias[t];
        const int i = t >> 3;
        const int c = t & 7;
        const float4 xv = *(const float4*)(x + (((b * II + i) * CC + c) << 8) + pix0);
        s_sx[0 * 256 + t] = xv.x;
        s_sx[1 * 256 + t] = xv.y;
        s_sx[2 * 256 + t] = xv.z;
        s_sx[3 * 256 + t] = xv.w;
    }
    __syncthreads();

    // ---- phase 1: votes -> smem. Role: mg = t&63 owns m quad [4mg,4mg+4);
    //      gi = t>>6 owns i pair {2gi, 2gi+1}. Weights load as LDG.128. ----
    {
        const int mg = t & 63;
        const int m0 = mg << 2;
        const int gi = t >> 6;
        #pragma unroll
        for (int iq = 0; iq < 2; ++iq) {
            const int i = 2 * gi + iq;
            const float4* wp4 = (const float4*)(w + (i * CC) * MM + m0);
            float4 wr[CC];
            #pragma unroll
            for (int c = 0; c < CC; ++c) wr[c] = wp4[c * (MM / 4)];   // coalesced 16B/lane
            #pragma unroll
            for (int p = 0; p < PPB; ++p) {
                const float4* sx4 = (const float4*)(s_sx + p * 256 + i * 8);
                float4 xa = sx4[0], xb = sx4[1];                      // broadcast
                float a0 = 0.f, a1 = 0.f, a2 = 0.f, a3 = 0.f;
                #define VSTEP(xc, c) \
                    a0 += (xc) * wr[c].x; a1 += (xc) * wr[c].y; \
                    a2 += (xc) * wr[c].z; a3 += (xc) * wr[c].w;
                VSTEP(xa.x, 0) VSTEP(xa.y, 1) VSTEP(xa.z, 2) VSTEP(xa.w, 3)
                VSTEP(xb.x, 4) VSTEP(xb.y, 5) VSTEP(xb.z, 6) VSTEP(xb.w, 7)
                #undef VSTEP
                *(float4*)(s_votes + p * VP + i * 256 + m0) = make_float4(a0, a1, a2, a3);
            }
        }
    }
    __syncthreads();

    // ---- phase 2: group g owns pixel p = g entirely (its own barrier domain) ----
    const int p  = g;
    const int tg = t & 255;
    float v[II];
    #pragma unroll
    for (int i = 0; i < II; ++i) v[i] = s_votes[p * VP + i * 256 + m];  // lanes consecutive m: clean

    float act;

    // ======== iteration 0: route is uniformly 1/16 (softmax of zeros) ========
    {
        float a0 = 0.f, a1 = 0.f, a2 = 0.f, a3 = 0.f;
        #pragma unroll
        for (int q = 0; q < 8; ++q) {
            a0 += v[4 * q + 0];
            a1 += v[4 * q + 1];
            a2 += v[4 * q + 2];
            a3 += v[4 * q + 3];
        }
        float acc = s_bias[m] + ((a0 + a1) + (a2 + a3)) * 0.0625f;

        float ns = acc * acc;
        ns += __shfl_xor_sync(0xffffffffu, ns, 1);
        ns += __shfl_xor_sync(0xffffffffu, ns, 2);
        ns += __shfl_xor_sync(0xffffffffu, ns, 4);
        ns += __shfl_xor_sync(0xffffffffu, ns, 8);
        float nrm   = ns * frsq_(ns);
        float scale = nrm * frcp_(1.0f + ns);
        act = acc * scale;

        // distance -> WRITE logits
        #pragma unroll
        for (int half = 0; half < 2; ++half) {
            float dv[16];
            #pragma unroll
            for (int j = 0; j < 16; ++j) dv[j] = v[half * 16 + j] * act;
            {   int hb = hh & 1;
                #pragma unroll
                for (int j = 0; j < 8; ++j) {
                    float send = hb ? dv[j] : dv[j + 8];
                    float recv = __shfl_xor_sync(0xffffffffu, send, 1);
                    dv[j] = (hb ? dv[j + 8] : dv[j]) + recv;
                } }
            {   int hb = (hh >> 1) & 1;
                #pragma unroll
                for (int j = 0; j < 4; ++j) {
                    float send = hb ? dv[j] : dv[j + 4];
                    float recv = __shfl_xor_sync(0xffffffffu, send, 2);
                    dv[j] = (hb ? dv[j + 4] : dv[j]) + recv;
                } }
            {   int hb = (hh >> 2) & 1;
                #pragma unroll
                for (int j = 0; j < 2; ++j) {
                    float send = hb ? dv[j] : dv[j + 2];
                    float recv = __shfl_xor_sync(0xffffffffu, send, 4);
                    dv[j] = (hb ? dv[j + 2] : dv[j]) + recv;
                } }
            {   int hb = (hh >> 3) & 1;
                float send = hb ? dv[0] : dv[1];
                float recv = __shfl_xor_sync(0xffffffffu, send, 8);
                dv[0] = (hb ? dv[1] : dv[0]) + recv;
            }
            s_log[p * LP + (half * 16 + irev) * LROW + o] = dv[0];
        }
    }
    BARG(g);

    // ======== iterations 1..NROUTE-1 (all group-local) ========
    #pragma unroll
    for (int r = 1; r < NROUTE; ++r) {
        // softmax over O, group-local: 32 rows (i) x 8 threads
        {
            const int si = tg >> 3;           // 0..31
            const int j  = tg & 7;
            const float* lg = s_log + p * LP + si * LROW;
            float l0 = lg[j];
            float l1 = lg[j + 8];
            float mx = fmaxf(l0, l1);
            mx = fmaxf(mx, __shfl_xor_sync(0xffffffffu, mx, 1));
            mx = fmaxf(mx, __shfl_xor_sync(0xffffffffu, mx, 2));
            mx = fmaxf(mx, __shfl_xor_sync(0xffffffffu, mx, 4));
            float e0 = __expf(l0 - mx);
            float e1 = __expf(l1 - mx);
            float s = e0 + e1;
            s += __shfl_xor_sync(0xffffffffu, s, 1);
            s += __shfl_xor_sync(0xffffffffu, s, 2);
            s += __shfl_xor_sync(0xffffffffu, s, 4);
            float inv = frcp_(s);
            float* rt = s_route + p * RP;
            rt[j * RROW + si]       = e0 * inv;
            rt[(j + 8) * RROW + si] = e1 * inv;
        }
        BARG(g);

        // preact: in-register reduce over all 32 i (4 independent FMA chains)
        {
            const float4* rp = (const float4*)(s_route + p * RP + o * RROW);
            float a0 = 0.f, a1 = 0.f, a2 = 0.f, a3 = 0.f;
            #pragma unroll
            for (int q = 0; q < 8; ++q) {
                float4 r4 = rp[q];                // broadcast
                a0 += r4.x * v[4 * q + 0];
                a1 += r4.y * v[4 * q + 1];
                a2 += r4.z * v[4 * q + 2];
                a3 += r4.w * v[4 * q + 3];
            }
            float acc = s_bias[m] + ((a0 + a1) + (a2 + a3));
            float ns = acc * acc;
            ns += __shfl_xor_sync(0xffffffffu, ns, 1);
            ns += __shfl_xor_sync(0xffffffffu, ns, 2);
            ns += __shfl_xor_sync(0xffffffffu, ns, 4);
            ns += __shfl_xor_sync(0xffffffffu, ns, 8);
            float nrm   = ns * frsq_(ns);
            float scale = nrm * frcp_(1.0f + ns);
            act = acc * scale;
        }

        if (r < NROUTE - 1) {
            // distance -> ACCUMULATE logits
            #pragma unroll
            for (int half = 0; half < 2; ++half) {
                float dv[16];
                #pragma unroll
                for (int j = 0; j < 16; ++j) dv[j] = v[half * 16 + j] * act;
                {   int hb = hh & 1;
                    #pragma unroll
                    for (int j = 0; j < 8; ++j) {
                        float send = hb ? dv[j] : dv[j + 8];
                        float recv = __shfl_xor_sync(0xffffffffu, send, 1);
                        dv[j] = (hb ? dv[j + 8] : dv[j]) + recv;
                    } }
                {   int hb = (hh >> 1) & 1;
                    #pragma unroll
                    for (int j = 0; j < 4; ++j) {
                        float send = hb ? dv[j] : dv[j + 4];
                        float recv = __shfl_xor_sync(0xffffffffu, send, 2);
                        dv[j] = (hb ? dv[j + 4] : dv[j]) + recv;
                    } }
                {   int hb = (hh >> 2) & 1;
                    #pragma unroll
                    for (int j = 0; j < 2; ++j) {
                        float send = hb ? dv[j] : dv[j + 2];
                        float recv = __shfl_xor_sync(0xffffffffu, send, 4);
                        dv[j] = (hb ? dv[j + 2] : dv[j]) + recv;
                    } }
                {   int hb = (hh >> 3) & 1;
                    float send = hb ? dv[0] : dv[1];
                    float recv = __shfl_xor_sync(0xffffffffu, send, 8);
                    dv[0] = (hb ? dv[1] : dv[0]) + recv;
                }
                s_log[p * LP + (half * 16 + irev) * LROW + o] += dv[0];
            }
            BARG(g);
        }
    }

    // ---- stage act through smem (alias over dead s_sx) and store coalesced ----
    float* s_act = s_sx;               // s_sx is dead after phase 1
    s_act[p * 256 + m] = act;
    __syncthreads();                   // cross-group: re-converges all domains
    if (t < MM) {
        float4 o4 = make_float4(s_act[0 * 256 + t], s_act[1 * 256 + t],
                                s_act[2 * 256 + t], s_act[3 * 256 + t]);
        *(float4*)(out + ((b * MM + t) << 8) + pix0) = o4;
    }
}

extern "C" void kernel_launch(void* const* d_in, const int* in_sizes, int n_in,
                              void* d_out, int out_size)
{
    const float* x    = (const float*)d_in[0];   // (8,32,8,16,16)
    const float* w    = (const float*)d_in[1];   // (32,8,256)
    const float* bias = (const float*)d_in[2];   // (16,16,1,1)
    float* out = (float*)d_out;                  // (8,16,16,16,16)

    static bool attr_set = false;
    if (!attr_set) {
        cudaFuncSetAttribute(caps_routing_kernel,
                             cudaFuncAttributeMaxDynamicSharedMemorySize,
                             SM_TOTAL * (int)sizeof(float));
        attr_set = true;
    }

    const int n_pixels = BB * HW;                 // 2048
    dim3 grid(n_pixels / PPB);                    // 512
    dim3 block(THREADS);
    caps_routing_kernel<<<grid, block, SM_TOTAL * (int)sizeof(float)>>>(x, w, bias, out);
}